// round 2
// baseline (speedup 1.0000x reference)
#include <cuda_runtime.h>
#include <math.h>

#define BATCH 2048
#define LSEQ  70
#define DIN   15
#define HID   16
#define NF    4
#define KW    40
#define CDIM  20          // DIN + 1 + NF
#define LP    31          // LSEQ - KW + 1
#define Z0    64
#define NOUT  128         // 2*Z0
#define SIGCH 8420        // C + C^2 + C^3

#define KSPLIT 18
#define KCHUNK 480        // 18*480 = 8640 >= 8420, 15 x KB
#define KB     32
#define NIT    (KCHUNK / KB)   // 15
#define TM     128
#define TN     128

// smem strides for gemm (floats / float2s)
#define ASTRIDE 130       // row stride of As (floats), padded, even
#define BSTRIDE 129       // row stride of Bs (float2), padded

// Scratch (static device arrays: allocation-free per harness rules)
__device__ float g_sig[(size_t)BATCH * SIGCH];            // 69 MB
__device__ float g_zpart[(size_t)KSPLIT * BATCH * NOUT];  // 18.9 MB

// Packed dual-FMA (Blackwell f32x2): acc = a*b + acc, SIMD over the pair
#define FFMA2(acc, a, b) \
    asm("fma.rn.f32x2 %0, %1, %2, %0;" : "+l"(acc) : "l"(a), "l"(b))

// ---------------------------------------------------------------------------
// Kernel 1: per-batch path (conv chain) + depth-3 signature
// One block per batch, 224 threads. No barriers inside the scan loop.
// ---------------------------------------------------------------------------
__global__ __launch_bounds__(224) void sig_kernel(
    const float* __restrict__ x,    // (B, L, DIN)
    const float* __restrict__ w1,   // (HID, DIN, KW)
    const float* __restrict__ b1,
    const float* __restrict__ w2,   // (HID, HID)
    const float* __restrict__ b2,
    const float* __restrict__ w3,   // (NF, HID)
    const float* __restrict__ b3)
{
    __shared__ float xs[(LSEQ + 1) * DIN];               // 1065 (+pad row)
    __shared__ float h1s[HID * LP];                      // 496
    __shared__ float paths[LP * CDIM];                   // 620
    __shared__ float h2s[HID * LP];                      // 496
    __shared__ __align__(16) float dsm[LP * CDIM];       // 620 increments

    const int b = blockIdx.x;
    const int t = threadIdx.x;

    // ---- load x[b] into smem ----
    for (int i = t; i < LSEQ * DIN; i += 224) xs[i] = x[(size_t)b * LSEQ * DIN + i];
    if (t < DIN) xs[LSEQ * DIN + t] = 0.f;               // pad row
    __syncthreads();

    // ---- conv1 (VALID, kernel 40), weights streamed from L1/L2 ----
    if (t < 128) {
        const int o  = t >> 3;
        const int l0 = (t & 7) * 4;
        float a0 = 0.f, a1 = 0.f, a2 = 0.f, a3 = 0.f;
        const float* wrow = w1 + o * DIN * KW;
        for (int c = 0; c < DIN; ++c) {
            float xw0 = xs[(l0 + 0) * DIN + c];
            float xw1 = xs[(l0 + 1) * DIN + c];
            float xw2 = xs[(l0 + 2) * DIN + c];
            const float* wc = wrow + c * KW;
            #pragma unroll 8
            for (int k = 0; k < KW; ++k) {
                float xw3 = xs[(l0 + k + 3) * DIN + c];
                float w = __ldg(wc + k);
                a0 = fmaf(w, xw0, a0);
                a1 = fmaf(w, xw1, a1);
                a2 = fmaf(w, xw2, a2);
                a3 = fmaf(w, xw3, a3);
                xw0 = xw1; xw1 = xw2; xw2 = xw3;
            }
        }
        float bias = b1[o];
        if (l0 + 0 < LP) h1s[o * LP + l0 + 0] = fmaxf(a0 + bias, 0.f);
        if (l0 + 1 < LP) h1s[o * LP + l0 + 1] = fmaxf(a1 + bias, 0.f);
        if (l0 + 2 < LP) h1s[o * LP + l0 + 2] = fmaxf(a2 + bias, 0.f);
        if (l0 + 3 < LP) h1s[o * LP + l0 + 3] = fmaxf(a3 + bias, 0.f);
    }
    __syncthreads();

    // ---- conv2 (1x1) + relu ----
    for (int idx = t; idx < HID * LP; idx += 224) {
        int o = idx / LP, l = idx % LP;
        float s = b2[o];
        #pragma unroll
        for (int c2 = 0; c2 < HID; ++c2)
            s = fmaf(w2[o * HID + c2], h1s[c2 * LP + l], s);
        h2s[idx] = fmaxf(s, 0.f);
    }
    __syncthreads();

    // ---- conv3 (1x1) + assemble path [orig(15) | time(1) | conv_out(4)] ----
    for (int idx = t; idx < LP * CDIM; idx += 224) {
        int l = idx / CDIM, c = idx % CDIM;
        float v;
        if (c < DIN) {
            v = xs[(KW - 1 + l) * DIN + c];
        } else if (c == DIN) {
            v = (float)l * (1.0f / (LP - 1));
        } else {
            int f = c - DIN - 1;
            float s = b3[f];
            #pragma unroll
            for (int c2 = 0; c2 < HID; ++c2)
                s = fmaf(w3[f * HID + c2], h2s[c2 * LP + l], s);
            v = s;
        }
        paths[idx] = v;
    }
    __syncthreads();

    // ---- precompute ALL increments once (removes per-step barriers) ----
    for (int idx = t; idx < LP * CDIM; idx += 224) {
        int l = idx / CDIM;
        dsm[idx] = paths[idx] - (l ? paths[idx - CDIM] : 0.f);
    }
    __syncthreads();

    // ---- depth-3 signature (Chen), barrier-free scan ----
    const int i0 = t / CDIM;
    const int j0 = t % CDIM;
    float s1a = 0.f, s1b = 0.f, s2a = 0.f, s2b = 0.f;
    float s3a[CDIM], s3b[CDIM];
    #pragma unroll
    for (int k = 0; k < CDIM; ++k) { s3a[k] = 0.f; s3b[k] = 0.f; }

    if (t < 200) {
        #pragma unroll 1
        for (int s = 0; s < LP; ++s) {
            const float* dr = &dsm[s * CDIM];
            float dj  = dr[j0];
            float dia = dr[i0];
            float dib = dr[i0 + 10];
            float A0 = fmaf(dj, fmaf(dia, 1.f / 6.f, 0.5f * s1a), s2a);
            float A1 = fmaf(dj, fmaf(dib, 1.f / 6.f, 0.5f * s1b), s2b);
            s2a = fmaf(dj, fmaf(dia, 0.5f, s1a), s2a);
            s2b = fmaf(dj, fmaf(dib, 0.5f, s1b), s2b);
            s1a += dia;
            s1b += dib;
            const float4* dv4 = (const float4*)dr;
            #pragma unroll
            for (int q = 0; q < 5; ++q) {
                float4 dv = dv4[q];
                s3a[q*4+0] = fmaf(A0, dv.x, s3a[q*4+0]);
                s3a[q*4+1] = fmaf(A0, dv.y, s3a[q*4+1]);
                s3a[q*4+2] = fmaf(A0, dv.z, s3a[q*4+2]);
                s3a[q*4+3] = fmaf(A0, dv.w, s3a[q*4+3]);
                s3b[q*4+0] = fmaf(A1, dv.x, s3b[q*4+0]);
                s3b[q*4+1] = fmaf(A1, dv.y, s3b[q*4+1]);
                s3b[q*4+2] = fmaf(A1, dv.z, s3b[q*4+2]);
                s3b[q*4+3] = fmaf(A1, dv.w, s3b[q*4+3]);
            }
        }
    }

    // ---- write signature: [s1(20) | s2(400) | s3(8000)] ----
    size_t base = (size_t)b * SIGCH;
    if (t < CDIM) g_sig[base + t] = paths[(LP - 1) * CDIM + t];   // s1 telescopes
    if (t < 200) {
        g_sig[base + CDIM + t]       = s2a;
        g_sig[base + CDIM + 200 + t] = s2b;
        size_t s3base = base + CDIM + CDIM * CDIM;
        float4* oa = (float4*)&g_sig[s3base + (size_t)t * CDIM];
        float4* ob = (float4*)&g_sig[s3base + (size_t)(t + 200) * CDIM];
        #pragma unroll
        for (int q = 0; q < 5; ++q) {
            oa[q] = make_float4(s3a[q*4+0], s3a[q*4+1], s3a[q*4+2], s3a[q*4+3]);
            ob[q] = make_float4(s3b[q*4+0], s3b[q*4+1], s3b[q*4+2], s3b[q*4+3]);
        }
    }
}

// ---------------------------------------------------------------------------
// Kernel 2: split-K GEMM with packed f32x2 FMAs + double-buffered smem.
// z_part[kz] = sig_tile(128 x Kc) @ wout^T chunk -> 128x128
// smem: As k-major [kk][m] (m-pairs -> LDS.64 packed a), Bs duplicated
// (b,b) float2 [kk][n] (LDS.64 packed broadcast b).
// ---------------------------------------------------------------------------
__global__ __launch_bounds__(256) void gemm_kernel(const float* __restrict__ wout)
{
    extern __shared__ float sm[];
    float*  As0 = sm;
    float*  As1 = sm + KB * ASTRIDE;
    float2* Bs0 = (float2*)(sm + 2 * KB * ASTRIDE);
    float2* Bs1 = Bs0 + KB * BSTRIDE;

    const int m0    = blockIdx.x * TM;
    const int kbase = blockIdx.y * KCHUNK;
    const int t  = threadIdx.x;
    const int tx = t & 15;     // n lane: n = j*16 + tx
    const int ty = t >> 4;     // m group: m = ty*8 + 2*ip (+1)

    unsigned long long acc[4][8];
    #pragma unroll
    for (int i = 0; i < 4; ++i)
        #pragma unroll
        for (int j = 0; j < 8; ++j) acc[i][j] = 0ull;

    // fill-thread mapping (shared by A and B): idx = t + i*256
    // A: m = idx>>3 (0..127), q = idx&7, k = q*4..q*4+3
    // B: n = idx>>3,          q = idx&7, k = q*4..q*4+3
    float4 ra[4], rb[4];

    #define LOAD_TILE(k0)                                                     \
        {                                                                     \
            _Pragma("unroll")                                                 \
            for (int i = 0; i < 4; ++i) {                                     \
                int idx = t + i * 256;                                        \
                int r = idx >> 3, q = idx & 7;                                \
                int k = (k0) + q * 4;                                         \
                if (k < SIGCH) {                                              \
                    ra[i] = *(const float4*)&g_sig[(size_t)(m0 + r) * SIGCH + k]; \
                    rb[i] = *(const float4*)&wout[(size_t)r * SIGCH + k];     \
                } else {                                                      \
                    ra[i] = make_float4(0.f, 0.f, 0.f, 0.f);                  \
                    rb[i] = make_float4(0.f, 0.f, 0.f, 0.f);                  \
                }                                                             \
            }                                                                 \
        }

    #define STORE_TILE(Ad, Bd)                                                \
        {                                                                     \
            _Pragma("unroll")                                                 \
            for (int i = 0; i < 4; ++i) {                                     \
                int idx = t + i * 256;                                        \
                int r = idx >> 3, q = idx & 7;                                \
                (Ad)[(q * 4 + 0) * ASTRIDE + r] = ra[i].x;                    \
                (Ad)[(q * 4 + 1) * ASTRIDE + r] = ra[i].y;                    \
                (Ad)[(q * 4 + 2) * ASTRIDE + r] = ra[i].z;                    \
                (Ad)[(q * 4 + 3) * ASTRIDE + r] = ra[i].w;                    \
                (Bd)[(q * 4 + 0) * BSTRIDE + r] = make_float2(rb[i].x, rb[i].x); \
                (Bd)[(q * 4 + 1) * BSTRIDE + r] = make_float2(rb[i].y, rb[i].y); \
                (Bd)[(q * 4 + 2) * BSTRIDE + r] = make_float2(rb[i].z, rb[i].z); \
                (Bd)[(q * 4 + 3) * BSTRIDE + r] = make_float2(rb[i].w, rb[i].w); \
            }                                                                 \
        }

    // prologue
    LOAD_TILE(kbase);
    STORE_TILE(As0, Bs0);
    __syncthreads();

    for (int it = 0; it < NIT; ++it) {
        const float*  A = (it & 1) ? As1 : As0;
        const float2* B = (it & 1) ? Bs1 : Bs0;
        float*  An = (it & 1) ? As0 : As1;
        float2* Bn = (it & 1) ? Bs0 : Bs1;

        if (it + 1 < NIT) LOAD_TILE(kbase + (it + 1) * KB);

        #pragma unroll 8
        for (int kk = 0; kk < KB; ++kk) {
            unsigned long long a2[4], b2[8];
            #pragma unroll
            for (int i = 0; i < 4; ++i)
                a2[i] = *(const unsigned long long*)&A[kk * ASTRIDE + ty * 8 + 2 * i];
            #pragma unroll
            for (int j = 0; j < 8; ++j)
                b2[j] = *(const unsigned long long*)&B[kk * BSTRIDE + j * 16 + tx];
            #pragma unroll
            for (int i = 0; i < 4; ++i)
                #pragma unroll
                for (int j = 0; j < 8; ++j)
                    FFMA2(acc[i][j], a2[i], b2[j]);
        }

        if (it + 1 < NIT) STORE_TILE(An, Bn);
        __syncthreads();
    }

    float* zp = g_zpart + ((size_t)blockIdx.y * BATCH + m0) * NOUT;
    #pragma unroll
    for (int i = 0; i < 4; ++i)
        #pragma unroll
        for (int j = 0; j < 8; ++j) {
            float2 v = *(float2*)&acc[i][j];
            int m = ty * 8 + 2 * i;
            int n = j * 16 + tx;
            zp[(size_t)m * NOUT + n]       = v.x;
            zp[(size_t)(m + 1) * NOUT + n] = v.y;
        }
}

#define GEMM_SMEM (2 * KB * ASTRIDE * 4 + 2 * KB * BSTRIDE * 8)

// ---------------------------------------------------------------------------
// Kernel 3: reduce split-K partials + bias; mean | softplus(std)
// ---------------------------------------------------------------------------
__global__ __launch_bounds__(256) void epi_kernel(const float* __restrict__ bout,
                                                  float* __restrict__ out)
{
    int idx = blockIdx.x * 256 + threadIdx.x;
    if (idx >= BATCH * NOUT) return;
    int b = idx / NOUT, n = idx % NOUT;
    float s = bout[n];
    #pragma unroll
    for (int z = 0; z < KSPLIT; ++z)
        s += g_zpart[((size_t)z * BATCH + b) * NOUT + n];
    if (n < Z0) {
        out[(size_t)b * Z0 + n] = s;
    } else {
        float v = fmaxf(s, 0.f) + log1pf(expf(-fabsf(s)));   // stable softplus
        out[(size_t)BATCH * Z0 + (size_t)b * Z0 + (n - Z0)] = v;
    }
}

// ---------------------------------------------------------------------------
extern "C" void kernel_launch(void* const* d_in, const int* in_sizes, int n_in,
                              void* d_out, int out_size)
{
    const float* x    = (const float*)d_in[0];
    // d_in[1] = observed_tp (unused by the reference computation)
    const float* w1   = (const float*)d_in[2];
    const float* b1   = (const float*)d_in[3];
    const float* w2   = (const float*)d_in[4];
    const float* b2   = (const float*)d_in[5];
    const float* w3   = (const float*)d_in[6];
    const float* b3   = (const float*)d_in[7];
    const float* wout = (const float*)d_in[8];
    const float* bout = (const float*)d_in[9];
    float* out = (float*)d_out;

    cudaFuncSetAttribute(gemm_kernel,
                         cudaFuncAttributeMaxDynamicSharedMemorySize, GEMM_SMEM);

    sig_kernel<<<BATCH, 224>>>(x, w1, b1, w2, b2, w3, b3);
    gemm_kernel<<<dim3(BATCH / TM, KSPLIT), 256, GEMM_SMEM>>>(wout);
    epi_kernel<<<(BATCH * NOUT + 255) / 256, 256>>>(bout, out);
}

// round 5
// speedup vs baseline: 1.7456x; 1.7456x over previous
#include <cuda_runtime.h>
#include <math.h>

#define BATCH 2048
#define LSEQ  70
#define DIN   15
#define HID   16
#define NF    4
#define KW    40
#define CDIM  20          // DIN + 1 + NF
#define LP    31          // LSEQ - KW + 1
#define Z0    64
#define NOUT  128         // 2*Z0
#define SIGCH 8420        // C + C^2 + C^3

#define KSPLIT 18
#define KCHUNK 480        // 18*480 = 8640 >= 8420
#define KB     16
#define NIT    (KCHUNK / KB)   // 30
#define TM     128
#define TN     128

#define ASTRIDE 130       // row stride of As (floats), padded
#define BSTRIDE 129       // row stride of Bs (float2), padded

// Scratch (static device arrays: allocation-free per harness rules)
__device__ float g_sig[(size_t)BATCH * SIGCH];            // 69 MB
__device__ float g_zpart[(size_t)KSPLIT * BATCH * NOUT];  // 18.9 MB

// Packed dual-FMA (Blackwell f32x2): acc = a*b + acc
#define FFMA2(acc, a, b) \
    asm("fma.rn.f32x2 %0, %1, %2, %0;" : "+l"(acc) : "l"(a), "l"(b))

// ---------------------------------------------------------------------------
// Kernel 1: per-batch path (conv chain) + depth-3 signature
// One block per batch, 224 threads. w1 cached in smem; barrier-free scan.
// ---------------------------------------------------------------------------
__global__ __launch_bounds__(224, 4) void sig_kernel(
    const float* __restrict__ x,    // (B, L, DIN)
    const float* __restrict__ w1,   // (HID, DIN, KW)
    const float* __restrict__ b1,
    const float* __restrict__ w2,   // (HID, HID)
    const float* __restrict__ b2,
    const float* __restrict__ w3,   // (NF, HID)
    const float* __restrict__ b3)
{
    __shared__ float xs[(LSEQ + 1) * DIN];               // 1065 (+pad row)
    __shared__ float h1s[HID * LP];                      // 496
    __shared__ float paths[LP * CDIM];                   // 620
    __shared__ float h2s[HID * LP];                      // 496
    __shared__ __align__(16) float dsm[LP * CDIM];       // 620 increments
    __shared__ __align__(16) float w1s[HID * DIN * KW];  // 9600 = 38.4 KB

    const int b = blockIdx.x;
    const int t = threadIdx.x;

    // ---- load x[b] and w1 into smem (w1 via float4) ----
    for (int i = t; i < LSEQ * DIN; i += 224) xs[i] = x[(size_t)b * LSEQ * DIN + i];
    if (t < DIN) xs[LSEQ * DIN + t] = 0.f;               // pad row
    {
        const float4* w4 = (const float4*)w1;
        float4* s4 = (float4*)w1s;
        for (int i = t; i < HID * DIN * KW / 4; i += 224) s4[i] = w4[i];
    }
    __syncthreads();

    // ---- conv1 (VALID, kernel 40): 128 threads, sliding window, w float4 ----
    if (t < 128) {
        const int o  = t >> 3;
        const int l0 = (t & 7) * 4;
        float a0 = 0.f, a1 = 0.f, a2 = 0.f, a3 = 0.f;
        const float* wrow = &w1s[o * DIN * KW];
        #pragma unroll 1
        for (int c = 0; c < DIN; ++c) {
            float xw0 = xs[(l0 + 0) * DIN + c];
            float xw1 = xs[(l0 + 1) * DIN + c];
            float xw2 = xs[(l0 + 2) * DIN + c];
            const float4* wc4 = (const float4*)(wrow + c * KW);
            #pragma unroll
            for (int kq = 0; kq < KW / 4; ++kq) {
                float4 w4 = wc4[kq];
                float xw3;
                xw3 = xs[(l0 + 4*kq + 3) * DIN + c];
                a0 = fmaf(w4.x, xw0, a0); a1 = fmaf(w4.x, xw1, a1);
                a2 = fmaf(w4.x, xw2, a2); a3 = fmaf(w4.x, xw3, a3);
                xw0 = xw1; xw1 = xw2; xw2 = xw3;
                xw3 = xs[(l0 + 4*kq + 4) * DIN + c];
                a0 = fmaf(w4.y, xw0, a0); a1 = fmaf(w4.y, xw1, a1);
                a2 = fmaf(w4.y, xw2, a2); a3 = fmaf(w4.y, xw3, a3);
                xw0 = xw1; xw1 = xw2; xw2 = xw3;
                xw3 = xs[(l0 + 4*kq + 5) * DIN + c];
                a0 = fmaf(w4.z, xw0, a0); a1 = fmaf(w4.z, xw1, a1);
                a2 = fmaf(w4.z, xw2, a2); a3 = fmaf(w4.z, xw3, a3);
                xw0 = xw1; xw1 = xw2; xw2 = xw3;
                xw3 = xs[(l0 + 4*kq + 6) * DIN + c];
                a0 = fmaf(w4.w, xw0, a0); a1 = fmaf(w4.w, xw1, a1);
                a2 = fmaf(w4.w, xw2, a2); a3 = fmaf(w4.w, xw3, a3);
                xw0 = xw1; xw1 = xw2; xw2 = xw3;
            }
        }
        float bias = b1[o];
        if (l0 + 0 < LP) h1s[o * LP + l0 + 0] = fmaxf(a0 + bias, 0.f);
        if (l0 + 1 < LP) h1s[o * LP + l0 + 1] = fmaxf(a1 + bias, 0.f);
        if (l0 + 2 < LP) h1s[o * LP + l0 + 2] = fmaxf(a2 + bias, 0.f);
        if (l0 + 3 < LP) h1s[o * LP + l0 + 3] = fmaxf(a3 + bias, 0.f);
    }
    __syncthreads();

    // ---- conv2 (1x1) + relu ----
    for (int idx = t; idx < HID * LP; idx += 224) {
        int o = idx / LP, l = idx % LP;
        float s = b2[o];
        #pragma unroll
        for (int c2 = 0; c2 < HID; ++c2)
            s = fmaf(w2[o * HID + c2], h1s[c2 * LP + l], s);
        h2s[idx] = fmaxf(s, 0.f);
    }
    __syncthreads();

    // ---- conv3 (1x1) + assemble path [orig(15) | time(1) | conv_out(4)] ----
    for (int idx = t; idx < LP * CDIM; idx += 224) {
        int l = idx / CDIM, c = idx % CDIM;
        float v;
        if (c < DIN) {
            v = xs[(KW - 1 + l) * DIN + c];
        } else if (c == DIN) {
            v = (float)l * (1.0f / (LP - 1));
        } else {
            int f = c - DIN - 1;
            float s = b3[f];
            #pragma unroll
            for (int c2 = 0; c2 < HID; ++c2)
                s = fmaf(w3[f * HID + c2], h2s[c2 * LP + l], s);
            v = s;
        }
        paths[idx] = v;
    }
    __syncthreads();

    // ---- precompute ALL increments once ----
    for (int idx = t; idx < LP * CDIM; idx += 224) {
        int l = idx / CDIM;
        dsm[idx] = paths[idx] - (l ? paths[idx - CDIM] : 0.f);
    }
    __syncthreads();

    // ---- depth-3 signature (Chen), barrier-free scan ----
    const int i0 = t / CDIM;
    const int j0 = t % CDIM;
    float s1a = 0.f, s1b = 0.f, s2a = 0.f, s2b = 0.f;
    float s3a[CDIM], s3b[CDIM];
    #pragma unroll
    for (int k = 0; k < CDIM; ++k) { s3a[k] = 0.f; s3b[k] = 0.f; }

    if (t < 200) {
        #pragma unroll 2
        for (int s = 0; s < LP; ++s) {
            const float* dr = &dsm[s * CDIM];
            float dj  = dr[j0];
            float dia = dr[i0];
            float dib = dr[i0 + 10];
            float A0 = fmaf(dj, fmaf(dia, 1.f / 6.f, 0.5f * s1a), s2a);
            float A1 = fmaf(dj, fmaf(dib, 1.f / 6.f, 0.5f * s1b), s2b);
            s2a = fmaf(dj, fmaf(dia, 0.5f, s1a), s2a);
            s2b = fmaf(dj, fmaf(dib, 0.5f, s1b), s2b);
            s1a += dia;
            s1b += dib;
            const float4* dv4 = (const float4*)dr;
            #pragma unroll
            for (int q = 0; q < 5; ++q) {
                float4 dv = dv4[q];
                s3a[q*4+0] = fmaf(A0, dv.x, s3a[q*4+0]);
                s3a[q*4+1] = fmaf(A0, dv.y, s3a[q*4+1]);
                s3a[q*4+2] = fmaf(A0, dv.z, s3a[q*4+2]);
                s3a[q*4+3] = fmaf(A0, dv.w, s3a[q*4+3]);
                s3b[q*4+0] = fmaf(A1, dv.x, s3b[q*4+0]);
                s3b[q*4+1] = fmaf(A1, dv.y, s3b[q*4+1]);
                s3b[q*4+2] = fmaf(A1, dv.z, s3b[q*4+2]);
                s3b[q*4+3] = fmaf(A1, dv.w, s3b[q*4+3]);
            }
        }
    }

    // ---- write signature: [s1(20) | s2(400) | s3(8000)] ----
    size_t base = (size_t)b * SIGCH;
    if (t < CDIM) g_sig[base + t] = paths[(LP - 1) * CDIM + t];   // s1 telescopes
    if (t < 200) {
        g_sig[base + CDIM + t]       = s2a;
        g_sig[base + CDIM + 200 + t] = s2b;
        size_t s3base = base + CDIM + CDIM * CDIM;
        float4* oa = (float4*)&g_sig[s3base + (size_t)t * CDIM];
        float4* ob = (float4*)&g_sig[s3base + (size_t)(t + 200) * CDIM];
        #pragma unroll
        for (int q = 0; q < 5; ++q) {
            oa[q] = make_float4(s3a[q*4+0], s3a[q*4+1], s3a[q*4+2], s3a[q*4+3]);
            ob[q] = make_float4(s3b[q*4+0], s3b[q*4+1], s3b[q*4+2], s3b[q*4+3]);
        }
    }
}

// ---------------------------------------------------------------------------
// Kernel 2: split-K GEMM, packed f32x2 FMAs, double-buffered, KB=16
// (48.5 KB smem total -> 2 blocks/SM, 16 warps)
// ---------------------------------------------------------------------------
__global__ __launch_bounds__(256, 2) void gemm_kernel(const float* __restrict__ wout)
{
    extern __shared__ float sm[];
    float*  As0 = sm;
    float*  As1 = sm + KB * ASTRIDE;
    float2* Bs0 = (float2*)(sm + 2 * KB * ASTRIDE);
    float2* Bs1 = Bs0 + KB * BSTRIDE;

    const int m0    = blockIdx.x * TM;
    const int kbase = blockIdx.y * KCHUNK;
    const int t  = threadIdx.x;
    const int tx = t & 15;     // n lane: n = j*16 + tx
    const int ty = t >> 4;     // m group: m = ty*8 + 2*i (+1)

    unsigned long long acc[4][8];
    #pragma unroll
    for (int i = 0; i < 4; ++i)
        #pragma unroll
        for (int j = 0; j < 8; ++j) acc[i][j] = 0ull;

    // fill mapping: idx = t + i*256 (i<2); r = idx>>2 (0..127), q = idx&3, k = q*4
    float4 ra[2], rb[2];

    #define LOAD_TILE(k0)                                                     \
        {                                                                     \
            _Pragma("unroll")                                                 \
            for (int i = 0; i < 2; ++i) {                                     \
                int idx = t + i * 256;                                        \
                int r = idx >> 2, q = idx & 3;                                \
                int k = (k0) + q * 4;                                         \
                if (k < SIGCH) {                                              \
                    ra[i] = *(const float4*)&g_sig[(size_t)(m0 + r) * SIGCH + k]; \
                    rb[i] = *(const float4*)&wout[(size_t)r * SIGCH + k];     \
                } else {                                                      \
                    ra[i] = make_float4(0.f, 0.f, 0.f, 0.f);                  \
                    rb[i] = make_float4(0.f, 0.f, 0.f, 0.f);                  \
                }                                                             \
            }                                                                 \
        }

    #define STORE_TILE(Ad, Bd)                                                \
        {                                                                     \
            _Pragma("unroll")                                                 \
            for (int i = 0; i < 2; ++i) {                                     \
                int idx = t + i * 256;                                        \
                int r = idx >> 2, q = idx & 3;                                \
                (Ad)[(q * 4 + 0) * ASTRIDE + r] = ra[i].x;                    \
                (Ad)[(q * 4 + 1) * ASTRIDE + r] = ra[i].y;                    \
                (Ad)[(q * 4 + 2) * ASTRIDE + r] = ra[i].z;                    \
                (Ad)[(q * 4 + 3) * ASTRIDE + r] = ra[i].w;                    \
                (Bd)[(q * 4 + 0) * BSTRIDE + r] = make_float2(rb[i].x, rb[i].x); \
                (Bd)[(q * 4 + 1) * BSTRIDE + r] = make_float2(rb[i].y, rb[i].y); \
                (Bd)[(q * 4 + 2) * BSTRIDE + r] = make_float2(rb[i].z, rb[i].z); \
                (Bd)[(q * 4 + 3) * BSTRIDE + r] = make_float2(rb[i].w, rb[i].w); \
            }                                                                 \
        }

    LOAD_TILE(kbase);
    STORE_TILE(As0, Bs0);
    __syncthreads();

    for (int it = 0; it < NIT; ++it) {
        const float*  A = (it & 1) ? As1 : As0;
        const float2* B = (it & 1) ? Bs1 : Bs0;
        float*  An = (it & 1) ? As0 : As1;
        float2* Bn = (it & 1) ? Bs0 : Bs1;

        if (it + 1 < NIT) LOAD_TILE(kbase + (it + 1) * KB);

        #pragma unroll
        for (int kk = 0; kk < KB; ++kk) {
            unsigned long long a2[4], b2[8];
            #pragma unroll
            for (int i = 0; i < 4; ++i)
                a2[i] = *(const unsigned long long*)&A[kk * ASTRIDE + ty * 8 + 2 * i];
            #pragma unroll
            for (int j = 0; j < 8; ++j)
                b2[j] = *(const unsigned long long*)&B[kk * BSTRIDE + j * 16 + tx];
            #pragma unroll
            for (int i = 0; i < 4; ++i)
                #pragma unroll
                for (int j = 0; j < 8; ++j)
                    FFMA2(acc[i][j], a2[i], b2[j]);
        }

        if (it + 1 < NIT) STORE_TILE(An, Bn);
        __syncthreads();
    }

    float* zp = g_zpart + ((size_t)blockIdx.y * BATCH + m0) * NOUT;
    #pragma unroll
    for (int i = 0; i < 4; ++i)
        #pragma unroll
        for (int j = 0; j < 8; ++j) {
            float2 v = *(float2*)&acc[i][j];
            int m = ty * 8 + 2 * i;
            int n = j * 16 + tx;
            zp[(size_t)m * NOUT + n]       = v.x;
            zp[(size_t)(m + 1) * NOUT + n] = v.y;
        }
}

#define GEMM_SMEM (2 * KB * ASTRIDE * 4 + 2 * KB * BSTRIDE * 8)

// ---------------------------------------------------------------------------
// Kernel 3: reduce split-K partials + bias; mean | softplus(std)
// ---------------------------------------------------------------------------
__global__ __launch_bounds__(256) void epi_kernel(const float* __restrict__ bout,
                                                  float* __restrict__ out)
{
    int idx = blockIdx.x * 256 + threadIdx.x;
    if (idx >= BATCH * NOUT) return;
    int b = idx / NOUT, n = idx % NOUT;
    float s = bout[n];
    #pragma unroll
    for (int z = 0; z < KSPLIT; ++z)
        s += g_zpart[((size_t)z * BATCH + b) * NOUT + n];
    if (n < Z0) {
        out[(size_t)b * Z0 + n] = s;
    } else {
        float v = fmaxf(s, 0.f) + log1pf(expf(-fabsf(s)));   // stable softplus
        out[(size_t)BATCH * Z0 + (size_t)b * Z0 + (n - Z0)] = v;
    }
}

// ---------------------------------------------------------------------------
extern "C" void kernel_launch(void* const* d_in, const int* in_sizes, int n_in,
                              void* d_out, int out_size)
{
    const float* x    = (const float*)d_in[0];
    // d_in[1] = observed_tp (unused by the reference computation)
    const float* w1   = (const float*)d_in[2];
    const float* b1   = (const float*)d_in[3];
    const float* w2   = (const float*)d_in[4];
    const float* b2   = (const float*)d_in[5];
    const float* w3   = (const float*)d_in[6];
    const float* b3   = (const float*)d_in[7];
    const float* wout = (const float*)d_in[8];
    const float* bout = (const float*)d_in[9];
    float* out = (float*)d_out;

    cudaFuncSetAttribute(gemm_kernel,
                         cudaFuncAttributeMaxDynamicSharedMemorySize, GEMM_SMEM);

    sig_kernel<<<BATCH, 224>>>(x, w1, b1, w2, b2, w3, b3);
    gemm_kernel<<<dim3(BATCH / TM, KSPLIT), 256, GEMM_SMEM>>>(wout);
    epi_kernel<<<(BATCH * NOUT + 255) / 256, 256>>>(bout, out);
}